// round 14
// baseline (speedup 1.0000x reference)
#include <cuda_runtime.h>
#include <math.h>

// ---------------- problem constants ----------------
#define B_  4
#define S_  2048
#define D_  768
#define H_  12
#define HD_ 64
#define F_  3072
#define ROWS_ (B_ * S_)          // 8192
#define QKVW_ (3 * D_)           // 2304

// ---------------- device scratch (static, no allocation) ----------------
__device__ float g_h   [ROWS_ * D_];      // LN1 output
__device__ float g_P   [D_ * QKVW_];      // packed QKV weight [D, 3D]
__device__ float g_bP  [QKVW_];           // packed QKV bias
__device__ float g_qkv [ROWS_ * QKVW_];   // fused QKV activations
__device__ float g_o   [ROWS_ * D_];      // attention output (head-concat)
__device__ float g_a   [ROWS_ * D_];      // after O-proj
__device__ float g_h2  [ROWS_ * D_];      // LN2 output
__device__ float g_f   [ROWS_ * F_];      // FFN hidden

// ---------------- LayerNorm: one block per row (768), 256 threads ----------------
__global__ __launch_bounds__(256) void ln_kernel(
    const float* __restrict__ X, const float* __restrict__ gamma,
    const float* __restrict__ beta, float* __restrict__ Y)
{
    __shared__ float red[8];
    __shared__ float s_mu, s_rstd;
    int row = blockIdx.x;
    int tid = threadIdx.x;
    const float* x = X + (size_t)row * D_;

    float v0 = x[tid], v1 = x[tid + 256], v2 = x[tid + 512];
    float s = v0 + v1 + v2;
    #pragma unroll
    for (int o = 16; o > 0; o >>= 1) s += __shfl_down_sync(0xffffffffu, s, o);
    if ((tid & 31) == 0) red[tid >> 5] = s;
    __syncthreads();
    if (tid < 32) {
        float t = (tid < 8) ? red[tid] : 0.f;
        #pragma unroll
        for (int o = 4; o > 0; o >>= 1) t += __shfl_down_sync(0xffffffffu, t, o);
        if (tid == 0) s_mu = t * (1.f / 768.f);
    }
    __syncthreads();
    float mu = s_mu;
    float d0 = v0 - mu, d1 = v1 - mu, d2 = v2 - mu;
    float s2 = d0 * d0 + d1 * d1 + d2 * d2;
    #pragma unroll
    for (int o = 16; o > 0; o >>= 1) s2 += __shfl_down_sync(0xffffffffu, s2, o);
    if ((tid & 31) == 0) red[tid >> 5] = s2;
    __syncthreads();
    if (tid < 32) {
        float t = (tid < 8) ? red[tid] : 0.f;
        #pragma unroll
        for (int o = 4; o > 0; o >>= 1) t += __shfl_down_sync(0xffffffffu, t, o);
        if (tid == 0) s_rstd = rsqrtf(t * (1.f / 768.f) + 1e-5f);
    }
    __syncthreads();
    float r = s_rstd;
    float* y = Y + (size_t)row * D_;
    y[tid]       = d0 * r * gamma[tid]       + beta[tid];
    y[tid + 256] = d1 * r * gamma[tid + 256] + beta[tid + 256];
    y[tid + 512] = d2 * r * gamma[tid + 512] + beta[tid + 512];
}

// ---------------- pack Wq/Wk/Wv [H,D,HD] -> P [D, 3D] ----------------
__global__ void pack_w_kernel(const float* __restrict__ Wq, const float* __restrict__ Wk,
                              const float* __restrict__ Wv, float* __restrict__ P)
{
    int idx = blockIdx.x * blockDim.x + threadIdx.x;
    if (idx >= D_ * QKVW_) return;
    int d   = idx / QKVW_;
    int col = idx % QKVW_;
    int sec = col / D_;
    int r   = col % D_;
    int h   = r >> 6;
    int e   = r & 63;
    const float* W = (sec == 0) ? Wq : ((sec == 1) ? Wk : Wv);
    P[idx] = W[((size_t)h * D_ + d) * HD_ + e];
}

__global__ void pack_b_kernel(const float* __restrict__ bq, const float* __restrict__ bk,
                              const float* __restrict__ bv, float* __restrict__ Pb)
{
    int col = blockIdx.x * blockDim.x + threadIdx.x;
    if (col >= QKVW_) return;
    int sec = col / D_;
    int r   = col % D_;
    const float* bb = (sec == 0) ? bq : ((sec == 1) ? bk : bv);
    Pb[col] = bb[r];
}

// ---------------- tiled SGEMM: C = A[M,K] * B[K,N] + bias, optional GELU ----------------
// BM=BN=128, BK=16, 256 threads, 8x8 microtile. All dims are multiples of the tiles.
#define BM 128
#define BN 128
#define BK 16
#define TM 8
#define TN 8

template<int ACT>   // 0 = none, 1 = exact-erf GELU
__global__ __launch_bounds__(256) void sgemm_kernel(
    const float* __restrict__ A, const float* __restrict__ Bm,
    const float* __restrict__ bias, float* __restrict__ C,
    int M, int N, int K)
{
    __shared__ __align__(16) float As[BK][BM + 4];
    __shared__ __align__(16) float Bs[BK][BN];

    int tid = threadIdx.x;
    int n0 = blockIdx.x * BN;
    int m0 = blockIdx.y * BM;
    int tx = tid & 15;
    int ty = tid >> 4;

    float acc[TM][TN];
    #pragma unroll
    for (int i = 0; i < TM; i++)
        #pragma unroll
        for (int j = 0; j < TN; j++) acc[i][j] = 0.f;

    const float* Ap = A + (size_t)m0 * K;
    const float* Bp = Bm + n0;

    for (int k0 = 0; k0 < K; k0 += BK) {
        // load A tile (128x16) as float4, store transposed
        #pragma unroll
        for (int i = 0; i < 2; i++) {
            int f   = tid + i * 256;
            int row = f >> 2;
            int c4  = (f & 3) << 2;
            float4 v = *(const float4*)(Ap + (size_t)row * K + k0 + c4);
            As[c4 + 0][row] = v.x;
            As[c4 + 1][row] = v.y;
            As[c4 + 2][row] = v.z;
            As[c4 + 3][row] = v.w;
        }
        // load B tile (16x128) as float4
        #pragma unroll
        for (int i = 0; i < 2; i++) {
            int f   = tid + i * 256;
            int row = f >> 5;
            int c4  = (f & 31) << 2;
            float4 v = *(const float4*)(Bp + (size_t)(k0 + row) * N + c4);
            *(float4*)&Bs[row][c4] = v;
        }
        __syncthreads();

        #pragma unroll
        for (int k = 0; k < BK; k++) {
            float a[TM], bb[TN];
            #pragma unroll
            for (int i = 0; i < TM; i += 4)
                *(float4*)&a[i] = *(const float4*)&As[k][ty * TM + i];
            #pragma unroll
            for (int j = 0; j < TN; j += 4)
                *(float4*)&bb[j] = *(const float4*)&Bs[k][tx * TN + j];
            #pragma unroll
            for (int i = 0; i < TM; i++)
                #pragma unroll
                for (int j = 0; j < TN; j++)
                    acc[i][j] += a[i] * bb[j];
        }
        __syncthreads();
    }

    #pragma unroll
    for (int i = 0; i < TM; i++) {
        int m = m0 + ty * TM + i;
        #pragma unroll
        for (int j = 0; j < TN; j += 4) {
            int n = n0 + tx * TN + j;
            float4 v;
            v.x = acc[i][j + 0] + bias[n + 0];
            v.y = acc[i][j + 1] + bias[n + 1];
            v.z = acc[i][j + 2] + bias[n + 2];
            v.w = acc[i][j + 3] + bias[n + 3];
            if (ACT == 1) {
                v.x = 0.5f * v.x * (1.f + erff(v.x * 0.70710678118654752f));
                v.y = 0.5f * v.y * (1.f + erff(v.y * 0.70710678118654752f));
                v.z = 0.5f * v.z * (1.f + erff(v.z * 0.70710678118654752f));
                v.w = 0.5f * v.w * (1.f + erff(v.w * 0.70710678118654752f));
            }
            *(float4*)&C[(size_t)m * N + n] = v;
        }
    }
}

// ---------------- fused flash attention ----------------
// grid (S/64, H, B), 64 threads; 1 thread = 1 query row (q, o in registers)
// QKV layout per row (b*S+s): [Q(h,e) | K(h,e) | V(h,e)], each 768.
__global__ __launch_bounds__(64) void attn_kernel(const float* __restrict__ QKV,
                                                  float* __restrict__ O)
{
    __shared__ __align__(16) float Ks[32][64];
    __shared__ __align__(16) float Vs[32][64];

    int tid = threadIdx.x;
    int h = blockIdx.y, b = blockIdx.z;
    int qi = blockIdx.x * 64 + tid;

    const float* qp = QKV + ((size_t)(b * S_ + qi)) * QKVW_ + h * HD_;
    float4 q[16];
    #pragma unroll
    for (int i = 0; i < 16; i++) q[i] = ((const float4*)qp)[i];

    float4 o[16];
    #pragma unroll
    for (int i = 0; i < 16; i++) o[i] = make_float4(0.f, 0.f, 0.f, 0.f);
    float m = -1e30f, l = 0.f;

    const float* kbase = QKV + ((size_t)b * S_) * QKVW_ + D_ + h * HD_ + tid;
    const float* vbase = kbase + D_;

    for (int kt = 0; kt < S_; kt += 32) {
        __syncthreads();
        #pragma unroll
        for (int j = 0; j < 32; j++) {
            size_t off = (size_t)(kt + j) * QKVW_;
            Ks[j][tid] = kbase[off];
            Vs[j][tid] = vbase[off];
        }
        __syncthreads();

        float s[32];
        float tmax = -1e30f;
        #pragma unroll
        for (int j = 0; j < 32; j++) {
            const float4* kr = (const float4*)Ks[j];
            float acc = 0.f;
            #pragma unroll
            for (int d = 0; d < 16; d++) {
                float4 kv = kr[d];
                acc += q[d].x * kv.x + q[d].y * kv.y + q[d].z * kv.z + q[d].w * kv.w;
            }
            s[j] = acc * 0.125f;   // 1/sqrt(64)
            tmax = fmaxf(tmax, s[j]);
        }
        float mnew = fmaxf(m, tmax);
        float c = __expf(m - mnew);
        l *= c;
        #pragma unroll
        for (int i = 0; i < 16; i++) {
            o[i].x *= c; o[i].y *= c; o[i].z *= c; o[i].w *= c;
        }
        #pragma unroll
        for (int j = 0; j < 32; j++) {
            float p = __expf(s[j] - mnew);
            l += p;
            const float4* vr = (const float4*)Vs[j];
            #pragma unroll
            for (int d = 0; d < 16; d++) {
                float4 vv = vr[d];
                o[d].x += p * vv.x; o[d].y += p * vv.y;
                o[d].z += p * vv.z; o[d].w += p * vv.w;
            }
        }
        m = mnew;
    }

    float inv = 1.f / l;
    float* op = O + ((size_t)(b * S_ + qi)) * D_ + h * HD_;
    #pragma unroll
    for (int i = 0; i < 16; i++) {
        float4 vv = o[i];
        vv.x *= inv; vv.y *= inv; vv.z *= inv; vv.w *= inv;
        ((float4*)op)[i] = vv;
    }
}

// ---------------- host launcher ----------------
extern "C" void kernel_launch(void* const* d_in, const int* in_sizes, int n_in,
                              void* d_out, int out_size)
{
    (void)in_sizes; (void)n_in; (void)out_size;
    const float* x   = (const float*)d_in[0];
    const float* Wq  = (const float*)d_in[1];
    const float* bq  = (const float*)d_in[2];
    const float* Wk  = (const float*)d_in[3];
    const float* bk  = (const float*)d_in[4];
    const float* Wv  = (const float*)d_in[5];
    const float* bv  = (const float*)d_in[6];
    const float* Wo  = (const float*)d_in[7];
    const float* bo  = (const float*)d_in[8];
    const float* W1  = (const float*)d_in[9];
    const float* b1  = (const float*)d_in[10];
    const float* W2  = (const float*)d_in[11];
    const float* b2  = (const float*)d_in[12];
    const float* g1  = (const float*)d_in[13];
    const float* be1 = (const float*)d_in[14];
    const float* g2  = (const float*)d_in[15];
    const float* be2 = (const float*)d_in[16];
    float* out = (float*)d_out;

    void *ph, *pP, *pbP, *pqkv, *po, *pa, *ph2, *pf;
    cudaGetSymbolAddress(&ph,   g_h);
    cudaGetSymbolAddress(&pP,   g_P);
    cudaGetSymbolAddress(&pbP,  g_bP);
    cudaGetSymbolAddress(&pqkv, g_qkv);
    cudaGetSymbolAddress(&po,   g_o);
    cudaGetSymbolAddress(&pa,   g_a);
    cudaGetSymbolAddress(&ph2,  g_h2);
    cudaGetSymbolAddress(&pf,   g_f);
    float* h   = (float*)ph;
    float* P   = (float*)pP;
    float* bP  = (float*)pbP;
    float* qkv = (float*)pqkv;
    float* o   = (float*)po;
    float* a   = (float*)pa;
    float* h2  = (float*)ph2;
    float* f   = (float*)pf;

    // 1) LN1
    ln_kernel<<<ROWS_, 256>>>(x, g1, be1, h);
    // 2) pack QKV weights/bias
    pack_w_kernel<<<(D_ * QKVW_ + 255) / 256, 256>>>(Wq, Wk, Wv, P);
    pack_b_kernel<<<(QKVW_ + 255) / 256, 256>>>(bq, bk, bv, bP);
    // 3) fused QKV projection: [8192,768] x [768,2304]
    sgemm_kernel<0><<<dim3(QKVW_ / BN, ROWS_ / BM), 256>>>(h, P, bP, qkv, ROWS_, QKVW_, D_);
    // 4) attention
    attn_kernel<<<dim3(S_ / 64, H_, B_), 64>>>(qkv, o);
    // 5) output projection: [8192,768] x [768,768]
    sgemm_kernel<0><<<dim3(D_ / BN, ROWS_ / BM), 256>>>(o, Wo, bo, a, ROWS_, D_, D_);
    // 6) LN2
    ln_kernel<<<ROWS_, 256>>>(a, g2, be2, h2);
    // 7) FFN1 + GELU: [8192,768] x [768,3072]
    sgemm_kernel<1><<<dim3(F_ / BN, ROWS_ / BM), 256>>>(h2, W1, b1, f, ROWS_, F_, D_);
    // 8) FFN2: [8192,3072] x [3072,768] -> out
    sgemm_kernel<0><<<dim3(D_ / BN, ROWS_ / BM), 256>>>(f, W2, b2, out, ROWS_, D_, F_);
}